// round 8
// baseline (speedup 1.0000x reference)
#include <cuda_runtime.h>
#include <cuda_fp16.h>
#include <cstdint>

// Problem constants (fixed shapes)
#define NN 100000
#define EE 1600000
#define DD 128
#define HH 64
#define CC 10
#define GG 1024
#define SCAN_BLOCKS ((NN + 255) / 256)   // 391
#define NSPLIT 50048                     // lo/hi split: multiple of 128 and 16

// ---------------- scratch (device globals; no allocations allowed) ----------
__device__ __align__(16) __half g_bufA[NN * HH]; // fp16 GEMM output (layers 1,3)
__device__ __align__(16) __half g_bufC[NN * HH]; // fp16 GEMM output (layer 2)
__device__ __align__(16) __half g_bufBh[NN * HH];// fp16 gather output (GEMM input)
__device__ __align__(16) float g_dinv[NN];
__device__ __align__(16) float g_pool[GG * HH];
__device__ float g_cnt[GG];
__device__ int   g_degi[NN];
__device__ int   g_ptr[NN + 1];
__device__ int   g_cursor[NN];
__device__ int   g_bsum[512];
__device__ int   g_csr[EE];
__device__ int   g_is64;                          // 1 if indices are int64

// ---------------- side stream + events (host-side only) ------------------------
enum { EV_FORK = 0, EV_G1, EV_A, EV_B, EV_D, EV_E, EV_F, EV_H, EV_N };
struct SideStream {
    cudaStream_t s;
    cudaEvent_t ev[EV_N];
    SideStream() {
        cudaStreamCreateWithFlags(&s, cudaStreamNonBlocking);
        for (int i = 0; i < EV_N; ++i)
            cudaEventCreateWithFlags(&ev[i], cudaEventDisableTiming);
    }
};
static SideStream g_ss;

// ---------------- helpers ----------------------------------------------------
__device__ __forceinline__ int load_idx(const void* p, long long i) {
    if (g_is64) return (int)((const long long*)p)[i];
    return ((const int*)p)[i];
}

__device__ __forceinline__ void red_add_v4(float4* addr, float4 v) {
    asm volatile("red.global.add.v4.f32 [%0], {%1,%2,%3,%4};"
                 :: "l"(addr), "f"(v.x), "f"(v.y), "f"(v.z), "f"(v.w)
                 : "memory");
}

__device__ __forceinline__ void ldsm_x4(uint32_t* r, uint32_t addr) {
    asm volatile("ldmatrix.sync.aligned.m8n8.x4.shared.b16 {%0,%1,%2,%3}, [%4];"
                 : "=r"(r[0]), "=r"(r[1]), "=r"(r[2]), "=r"(r[3]) : "r"(addr));
}

__device__ __forceinline__ void ldsm_x4_t(uint32_t* r, uint32_t addr) {
    asm volatile("ldmatrix.sync.aligned.m8n8.x4.trans.shared.b16 {%0,%1,%2,%3}, [%4];"
                 : "=r"(r[0]), "=r"(r[1]), "=r"(r[2]), "=r"(r[3]) : "r"(addr));
}

__device__ __forceinline__ void mma_16816(float* d, const uint32_t* a, const uint32_t* b) {
    asm volatile("mma.sync.aligned.m16n8k16.row.col.f32.f16.f16.f32 "
                 "{%0,%1,%2,%3}, {%4,%5,%6,%7}, {%8,%9}, {%0,%1,%2,%3};"
                 : "+f"(d[0]), "+f"(d[1]), "+f"(d[2]), "+f"(d[3])
                 : "r"(a[0]), "r"(a[1]), "r"(a[2]), "r"(a[3]), "r"(b[0]), "r"(b[1]));
}

// ---------------- zero degi + dtype detect (fused) -----------------------------
__global__ void k_zero_detect(const unsigned int* __restrict__ w) {
    int i = blockIdx.x * blockDim.x + threadIdx.x;
    if (i < NN) g_degi[i] = 0;
    if (blockIdx.x == 0) {
        __shared__ unsigned int s[256];
        unsigned int acc = 0;
        const int stride = EE / (256 * 64);   // 97
        for (int j = 0; j < 64; ++j) {
            long long pair = (long long)(threadIdx.x * 64 + j) * stride;
            acc |= w[2 * pair + 1];
        }
        s[threadIdx.x] = acc;
        __syncthreads();
        for (int st = 128; st > 0; st >>= 1) {
            if (threadIdx.x < st) s[threadIdx.x] |= s[threadIdx.x + st];
            __syncthreads();
        }
        if (threadIdx.x == 0) g_is64 = (s[0] == 0u) ? 1 : 0;
    }
}

__global__ void k_zero_pool() {
    int i = blockIdx.x * blockDim.x + threadIdx.x;
    if (i < GG * HH) g_pool[i] = 0.0f;
    if (i < GG) g_cnt[i] = 0.0f;
}

// ---------------- degree histogram (4 edges/thread) ----------------------------
__global__ void k_deg_count(const void* ei) {
    long long e0 = 4LL * (blockIdx.x * blockDim.x + threadIdx.x);
    if (e0 >= EE) return;
    int c0, c1, c2, c3;
    if (g_is64) {
        const longlong2* p = (const longlong2*)((const long long*)ei + EE + e0);
        longlong2 a = p[0], b = p[1];
        c0 = (int)a.x; c1 = (int)a.y; c2 = (int)b.x; c3 = (int)b.y;
    } else {
        int4 v = *(const int4*)((const int*)ei + EE + e0);
        c0 = v.x; c1 = v.y; c2 = v.z; c3 = v.w;
    }
    atomicAdd(&g_degi[c0], 1);
    atomicAdd(&g_degi[c1], 1);
    atomicAdd(&g_degi[c2], 1);
    atomicAdd(&g_degi[c3], 1);
}

// ---------------- scan stage 1 (block-local) + dinv fused ----------------------
__global__ void k_scan1() {
    __shared__ int s[256];
    int i = blockIdx.x * 256 + threadIdx.x;
    int v = (i < NN) ? g_degi[i] : 0;
    if (i < NN) g_dinv[i] = rsqrtf((float)(v + 1));   // +1 self loop
    s[threadIdx.x] = v;
    __syncthreads();
    for (int off = 1; off < 256; off <<= 1) {
        int add = (threadIdx.x >= off) ? s[threadIdx.x - off] : 0;
        __syncthreads();
        s[threadIdx.x] += add;
        __syncthreads();
    }
    if (i < NN) g_ptr[i] = s[threadIdx.x] - v;
    if (threadIdx.x == 255) g_bsum[blockIdx.x] = s[255];
}

// ---------------- scan stages 2+3 fused: each block reduces its own prefix ------
__global__ void k_scan23() {
    __shared__ int red[256];
    int bid = blockIdx.x;
    int sum = 0;
    for (int b = threadIdx.x; b < bid; b += 256) sum += g_bsum[b];
    red[threadIdx.x] = sum;
    __syncthreads();
    for (int st = 128; st > 0; st >>= 1) {
        if (threadIdx.x < st) red[threadIdx.x] += red[threadIdx.x + st];
        __syncthreads();
    }
    int pref = red[0];
    int i = bid * 256 + threadIdx.x;
    if (i < NN) {
        int p = g_ptr[i] + pref;
        g_ptr[i] = p;
        g_cursor[i] = p;
    }
    if (i == 0) g_ptr[NN] = EE;
}

// ---------------- CSR fill: bucket rows by col (4 edges/thread) -----------------
__global__ void k_fill(const void* __restrict__ ei) {
    long long e0 = 4LL * (blockIdx.x * blockDim.x + threadIdx.x);
    if (e0 >= EE) return;
    int r0, r1, r2, r3, c0, c1, c2, c3;
    if (g_is64) {
        const longlong2* pr = (const longlong2*)((const long long*)ei + e0);
        const longlong2* pc = (const longlong2*)((const long long*)ei + EE + e0);
        longlong2 ra = pr[0], rb = pr[1], ca = pc[0], cb = pc[1];
        r0 = (int)ra.x; r1 = (int)ra.y; r2 = (int)rb.x; r3 = (int)rb.y;
        c0 = (int)ca.x; c1 = (int)ca.y; c2 = (int)cb.x; c3 = (int)cb.y;
    } else {
        int4 rv = *(const int4*)((const int*)ei + e0);
        int4 cv = *(const int4*)((const int*)ei + EE + e0);
        r0 = rv.x; r1 = rv.y; r2 = rv.z; r3 = rv.w;
        c0 = cv.x; c1 = cv.y; c2 = cv.z; c3 = cv.w;
    }
    g_csr[atomicAdd(&g_cursor[c0], 1)] = r0;
    g_csr[atomicAdd(&g_cursor[c1], 1)] = r1;
    g_csr[atomicAdd(&g_cursor[c2], 1)] = r2;
    g_csr[atomicAdd(&g_cursor[c3], 1)] = r3;
}

// ---------------- tensor-core GEMM: OUT = fp16([dinv ⊙] (X(N,K) @ W(K,64))) ----
// 256 threads / 8 warps, block tile 128 rows x 64 cols, K chunked by 64.
// OUTC: write g_bufC instead of g_bufA (ping-pong to avoid cross-layer races).
template <int K, bool FIRST, bool SCALE, bool OUTC>
__global__ void k_gemm_tc(const float* __restrict__ W, const float* __restrict__ Xf,
                          int blkoff) {
    constexpr int LDX = 72;   // 64 + 8 halfs pad
    __shared__ __half sX[128 * LDX];
    __shared__ __half sW[64 * LDX];

    __half* __restrict__ OUT = OUTC ? g_bufC : g_bufA;

    const int tid  = threadIdx.x;
    const int wid  = tid >> 5;
    const int lane = tid & 31;
    const int row0 = (blkoff + blockIdx.x) * 128;
    const int wr0  = wid * 16;          // warp row offset within tile

    float acc[8][4];
#pragma unroll
    for (int n = 0; n < 8; ++n)
#pragma unroll
        for (int i = 0; i < 4; ++i) acc[n][i] = 0.0f;

    const uint32_t sX_base = (uint32_t)__cvta_generic_to_shared(sX);
    const uint32_t sW_base = (uint32_t)__cvta_generic_to_shared(sW);

    for (int kt = 0; kt < K; kt += 64) {
        if (FIRST) {
            // fp32 global -> fp16 smem: 128 rows x 64 floats
#pragma unroll
            for (int it = 0; it < 8; ++it) {
                int idx = it * 256 + tid;        // 0..2047
                int r = idx >> 4, f4 = idx & 15;
                int grow = row0 + r;
                float4 v = make_float4(0.f, 0.f, 0.f, 0.f);
                if (grow < NN) v = *(const float4*)(Xf + (long long)grow * K + kt + f4 * 4);
                __half2 h0 = __floats2half2_rn(v.x, v.y);
                __half2 h1 = __floats2half2_rn(v.z, v.w);
                uint2 u;
                u.x = *(unsigned int*)&h0;
                u.y = *(unsigned int*)&h1;
                *(uint2*)(sX + r * LDX + f4 * 4) = u;
            }
        } else {
            // fp16 global -> smem: 128 rows x 64 halfs
#pragma unroll
            for (int it = 0; it < 4; ++it) {
                int idx = it * 256 + tid;        // 0..1023
                int r = idx >> 3, ch = idx & 7;
                int grow = row0 + r;
                uint4 u = make_uint4(0, 0, 0, 0);
                if (grow < NN) u = *(const uint4*)(g_bufBh + (long long)grow * K + kt + ch * 8);
                *(uint4*)(sX + r * LDX + ch * 8) = u;
            }
        }
        // load + convert W tile: 64 x 64
#pragma unroll
        for (int it = 0; it < 16; ++it) {
            int idx = it * 256 + tid;            // 0..4095
            int k = idx >> 6, n = idx & 63;
            sW[k * LDX + n] = __float2half(W[(kt + k) * HH + n]);
        }
        __syncthreads();

#pragma unroll
        for (int ks = 0; ks < 64; ks += 16) {
            uint32_t a[4];
            {
                int r = wr0 + (lane & 15);
                int kk = ks + ((lane >> 4) * 8);
                ldsm_x4(a, sX_base + (r * LDX + kk) * 2);
            }
#pragma unroll
            for (int np = 0; np < 4; ++np) {     // n-pairs: (np*16, np*16+8)
                uint32_t b[4];
                int krow = ks + (lane & 7) + (((lane >> 3) & 1) * 8);
                int ncol = np * 16 + ((lane >> 4) * 8);
                ldsm_x4_t(b, sW_base + (krow * LDX + ncol) * 2);
                mma_16816(acc[np * 2 + 0], a, b + 0);
                mma_16816(acc[np * 2 + 1], a, b + 2);
            }
        }
        __syncthreads();
    }

    // epilogue: optional dinv scale, store fp16
    const int rlo = row0 + wr0 + (lane >> 2);
    const int rhi = rlo + 8;
    const int cb  = (lane & 3) * 2;
    float dlo = 1.0f, dhi = 1.0f;
    if (SCALE) {
        dlo = (rlo < NN) ? g_dinv[rlo] : 0.0f;
        dhi = (rhi < NN) ? g_dinv[rhi] : 0.0f;
    }
#pragma unroll
    for (int nt = 0; nt < 8; ++nt) {
        int col = nt * 8 + cb;
        if (rlo < NN) {
            __half2 h = __floats2half2_rn(acc[nt][0] * dlo, acc[nt][1] * dlo);
            *(__half2*)(OUT + (long long)rlo * HH + col) = h;
        }
        if (rhi < NN) {
            __half2 h = __floats2half2_rn(acc[nt][2] * dhi, acc[nt][3] * dhi);
            *(__half2*)(OUT + (long long)rhi * HH + col) = h;
        }
    }
}

// ---------------- CSR gather ------------------------------------------------------
// 16 lanes per node, one 8B (4-half) channel chunk each. i0 = node offset.
// INC:   read g_bufC instead of g_bufA.
// RAWA:  input is raw XW; scale each neighbor by dinv[j] (shuffled alongside j).
// !LAST: bufBh[i] = fp16(dinv[i]*(selfterm + Σ w_j·IN[j]) + bias)
//  LAST: RED dinv[i]*(...) into g_pool[batch[i]] (+ cnt)
__device__ __forceinline__ void acc_half4(float4& acc, uint2 u, float s) {
    __half2 h0 = *(__half2*)&u.x;
    __half2 h1 = *(__half2*)&u.y;
    float2 f0 = __half22float2(h0);
    float2 f1 = __half22float2(h1);
    acc.x += f0.x * s; acc.y += f0.y * s; acc.z += f1.x * s; acc.w += f1.y * s;
}

template <bool LAST, bool RAWA, bool INC>
__global__ void k_gather(const float* __restrict__ bias, const void* __restrict__ batch,
                         int i0) {
    int t = blockIdx.x * blockDim.x + threadIdx.x;
    int i = i0 + (t >> 4);
    int c = t & 15;
    int lane = threadIdx.x & 31;
    int sub  = lane & 15;
    int base = lane & ~15;
    unsigned mask = 0xFFFFu << (lane & 16);

    int start = g_ptr[i];
    int end   = g_ptr[i + 1];

    float di = g_dinv[i];

    const uint2* __restrict__ A = INC ? (const uint2*)g_bufC : (const uint2*)g_bufA;
    float4 acc = make_float4(0.f, 0.f, 0.f, 0.f);
    acc_half4(acc, A[i * 16 + c], RAWA ? di : 1.0f);   // self loop

    for (int p0 = start; p0 < end; p0 += 16) {
        int myj = 0;
        float mydv = 0.0f;
        if (p0 + sub < end) {
            myj = g_csr[p0 + sub];
            if (RAWA) mydv = g_dinv[myj];
        }
        int cnt = min(16, end - p0);
        if (cnt == 16) {
#pragma unroll
            for (int k = 0; k < 16; ++k) {
                int j = __shfl_sync(mask, myj, k, 16);
                float dv = RAWA ? __shfl_sync(mask, mydv, k, 16) : 1.0f;
                acc_half4(acc, A[j * 16 + c], dv);
            }
        } else {
            for (int k = 0; k < cnt; ++k) {
                int j = __shfl_sync(mask, myj, k, 16);
                float dv = RAWA ? __shfl_sync(mask, mydv, k, 16) : 1.0f;
                acc_half4(acc, A[j * 16 + c], dv);
            }
        }
    }

    if (LAST) {
        float4 o;
        o.x = acc.x * di; o.y = acc.y * di; o.z = acc.z * di; o.w = acc.w * di;
        int b = 0;
        if (sub == 0) b = load_idx(batch, i);
        b = __shfl_sync(0xffffffffu, b, base);
        red_add_v4((float4*)&g_pool[b * HH + c * 4], o);
        if (c == 0) atomicAdd(&g_cnt[b], 1.0f);
    } else {
        float4 bv = ((const float4*)bias)[c];
        __half2 h0 = __floats2half2_rn(acc.x * di + bv.x, acc.y * di + bv.y);
        __half2 h1 = __floats2half2_rn(acc.z * di + bv.z, acc.w * di + bv.w);
        uint2 u;
        u.x = *(unsigned int*)&h0;
        u.y = *(unsigned int*)&h1;
        ((uint2*)g_bufBh)[i * 16 + c] = u;
    }
}

// ---------------- head: out(G,C) = (pool/cnt + b3) @ Wl + bl --------------------
__global__ void k_final(const float* __restrict__ Wl, const float* __restrict__ bl,
                        const float* __restrict__ b3, float* __restrict__ out) {
    int t = blockIdx.x * blockDim.x + threadIdx.x;
    if (t >= GG * CC) return;
    int g = t / CC, c = t % CC;
    float cnt = g_cnt[g];
    float inv = (cnt > 0.0f) ? (1.0f / cnt) : 0.0f;
    float sel = (cnt > 0.0f) ? 1.0f : 0.0f;
    float dot = 0.0f;
#pragma unroll
    for (int h = 0; h < HH; ++h)
        dot += (g_pool[g * HH + h] * inv + b3[h] * sel) * Wl[h * CC + c];
    out[t] = dot + bl[c];
}

// ---------------- launch ---------------------------------------------------------
extern "C" void kernel_launch(void* const* d_in, const int* in_sizes, int n_in,
                              void* d_out, int out_size) {
    const float* x  = (const float*)d_in[0];
    const void*  ei = d_in[1];
    const void*  bt = d_in[2];
    const float* W1 = (const float*)d_in[3];
    const float* b1 = (const float*)d_in[4];
    const float* W2 = (const float*)d_in[5];
    const float* b2 = (const float*)d_in[6];
    const float* W3 = (const float*)d_in[7];
    const float* b3 = (const float*)d_in[8];
    const float* Wl = (const float*)d_in[9];
    const float* bl = (const float*)d_in[10];
    float* out = (float*)d_out;

    const int TPB   = 256;
    const int gN    = (NN + TPB - 1) / TPB;           // 391
    const int gE4   = (EE / 4 + TPB - 1) / TPB;       // 1563
    const int gGemm  = (NN + 127) / 128;              // 782 (full)
    const int gGemmL = NSPLIT / 128;                  // 391 (lo)
    const int gGemmH = gGemm - gGemmL;                // 391 (hi, guarded)
    const int gGthL  = NSPLIT * 16 / TPB;             // 3128 (lo nodes)
    const int gGthH  = (NN - NSPLIT) * 16 / TPB;      // 3122 (hi nodes)
    const int gGthF  = NN * 16 / TPB;                 // 6250 (full)
    const int gPoolZ = (GG * HH + TPB - 1) / TPB;     // 256

    cudaStream_t s1 = g_ss.s;
    cudaEvent_t* ev = g_ss.ev;

    // ---- fork: side stream runs pool-zero + raw GEMM1 (independent of CSR) ----
    cudaEventRecord(ev[EV_FORK], 0);
    cudaStreamWaitEvent(s1, ev[EV_FORK], 0);
    k_zero_pool<<<gPoolZ, TPB, 0, s1>>>();
    k_gemm_tc<DD, true, false, false><<<gGemm, TPB, 0, s1>>>(W1, x, 0);  // -> bufA
    cudaEventRecord(ev[EV_G1], s1);

    // ---- main stream: CSR build chain ----
    k_zero_detect<<<gN, TPB>>>((const unsigned int*)ei);
    k_deg_count  <<<gE4, TPB>>>(ei);
    k_scan1      <<<SCAN_BLOCKS, 256>>>();
    k_scan23     <<<SCAN_BLOCKS, 256>>>();
    k_fill       <<<gE4, TPB>>>(ei);

    // ---- layer 1 gather (RAWA, reads bufA), split lo/hi ----
    cudaStreamWaitEvent(0, ev[EV_G1], 0);
    k_gather<false, true, false><<<gGthL, TPB>>>(b1, nullptr, 0);
    cudaEventRecord(ev[EV_A], 0);
    k_gather<false, true, false><<<gGthH, TPB>>>(b1, nullptr, NSPLIT);
    cudaEventRecord(ev[EV_B], 0);

    // ---- layer 2 GEMM (writes bufC) on side stream; lo overlaps gather1_hi ----
    cudaStreamWaitEvent(s1, ev[EV_A], 0);
    k_gemm_tc<HH, false, true, true><<<gGemmL, TPB, 0, s1>>>(W2, nullptr, 0);
    cudaStreamWaitEvent(s1, ev[EV_B], 0);
    k_gemm_tc<HH, false, true, true><<<gGemmH, TPB, 0, s1>>>(W2, nullptr, gGemmL);
    cudaEventRecord(ev[EV_D], s1);

    // ---- layer 2 gather (reads bufC), split lo/hi ----
    cudaStreamWaitEvent(0, ev[EV_D], 0);
    k_gather<false, false, true><<<gGthL, TPB>>>(b2, nullptr, 0);
    cudaEventRecord(ev[EV_E], 0);
    k_gather<false, false, true><<<gGthH, TPB>>>(b2, nullptr, NSPLIT);
    cudaEventRecord(ev[EV_F], 0);

    // ---- layer 3 GEMM (writes bufA) on side stream; lo overlaps gather2_hi ----
    cudaStreamWaitEvent(s1, ev[EV_E], 0);
    k_gemm_tc<HH, false, true, false><<<gGemmL, TPB, 0, s1>>>(W3, nullptr, 0);
    cudaStreamWaitEvent(s1, ev[EV_F], 0);
    k_gemm_tc<HH, false, true, false><<<gGemmH, TPB, 0, s1>>>(W3, nullptr, gGemmL);
    cudaEventRecord(ev[EV_H], s1);

    // ---- layer 3 gather (reads bufA) fused with mean-pool; head ----
    cudaStreamWaitEvent(0, ev[EV_H], 0);
    k_gather<true, false, false><<<gGthF, TPB>>>(nullptr, bt, 0);
    k_final<<<(GG * CC + TPB - 1) / TPB, TPB>>>(Wl, bl, b3, out);
}

// round 9
// speedup vs baseline: 1.0841x; 1.0841x over previous
#include <cuda_runtime.h>
#include <cuda_fp16.h>
#include <cstdint>

// Problem constants (fixed shapes)
#define NN 100000
#define EE 1600000
#define DD 128
#define HH 64
#define CC 10
#define GG 1024
#define SCAN_BLOCKS ((NN + 255) / 256)   // 391

// ---------------- scratch (device globals; no allocations allowed) ----------
__device__ __align__(16) __half g_bufA[NN * HH]; // fp16: dinv * (X @ W)
__device__ __align__(16) __half g_bufBh[NN * HH];// fp16 gather output (GEMM input)
__device__ __align__(16) float g_dinv[NN];
__device__ __align__(16) float g_pool[GG * HH];
__device__ float g_cnt[GG];
__device__ int   g_degi[NN];
__device__ int   g_ptr[NN + 1];
__device__ int   g_cursor[NN];
__device__ int   g_bsum[512];
__device__ int   g_csr[EE];
__device__ int   g_is64;                          // 1 if indices are int64

// ---------------- helpers ----------------------------------------------------
__device__ __forceinline__ int load_idx(const void* p, long long i) {
    if (g_is64) return (int)((const long long*)p)[i];
    return ((const int*)p)[i];
}

__device__ __forceinline__ void red_add_v4(float4* addr, float4 v) {
    asm volatile("red.global.add.v4.f32 [%0], {%1,%2,%3,%4};"
                 :: "l"(addr), "f"(v.x), "f"(v.y), "f"(v.z), "f"(v.w)
                 : "memory");
}

__device__ __forceinline__ void ldsm_x4(uint32_t* r, uint32_t addr) {
    asm volatile("ldmatrix.sync.aligned.m8n8.x4.shared.b16 {%0,%1,%2,%3}, [%4];"
                 : "=r"(r[0]), "=r"(r[1]), "=r"(r[2]), "=r"(r[3]) : "r"(addr));
}

__device__ __forceinline__ void ldsm_x4_t(uint32_t* r, uint32_t addr) {
    asm volatile("ldmatrix.sync.aligned.m8n8.x4.trans.shared.b16 {%0,%1,%2,%3}, [%4];"
                 : "=r"(r[0]), "=r"(r[1]), "=r"(r[2]), "=r"(r[3]) : "r"(addr));
}

__device__ __forceinline__ void mma_16816(float* d, const uint32_t* a, const uint32_t* b) {
    asm volatile("mma.sync.aligned.m16n8k16.row.col.f32.f16.f16.f32 "
                 "{%0,%1,%2,%3}, {%4,%5,%6,%7}, {%8,%9}, {%0,%1,%2,%3};"
                 : "+f"(d[0]), "+f"(d[1]), "+f"(d[2]), "+f"(d[3])
                 : "r"(a[0]), "r"(a[1]), "r"(a[2]), "r"(a[3]), "r"(b[0]), "r"(b[1]));
}

// ---------------- zero everything + dtype detect (fused, 1 launch) -------------
__global__ void k_zero_all(const unsigned int* __restrict__ w) {
    int i = blockIdx.x * blockDim.x + threadIdx.x;
    if (i < NN) g_degi[i] = 0;
    if (i < GG * HH) g_pool[i] = 0.0f;
    if (i < GG) g_cnt[i] = 0.0f;
    if (blockIdx.x == 0) {
        __shared__ unsigned int s[256];
        unsigned int acc = 0;
        const int stride = EE / (256 * 64);   // 97
        for (int j = 0; j < 64; ++j) {
            long long pair = (long long)(threadIdx.x * 64 + j) * stride;
            acc |= w[2 * pair + 1];
        }
        s[threadIdx.x] = acc;
        __syncthreads();
        for (int st = 128; st > 0; st >>= 1) {
            if (threadIdx.x < st) s[threadIdx.x] |= s[threadIdx.x + st];
            __syncthreads();
        }
        if (threadIdx.x == 0) g_is64 = (s[0] == 0u) ? 1 : 0;
    }
}

// ---------------- degree histogram (4 edges/thread) ----------------------------
__global__ void k_deg_count(const void* ei) {
    long long e0 = 4LL * (blockIdx.x * blockDim.x + threadIdx.x);
    if (e0 >= EE) return;
    int c0, c1, c2, c3;
    if (g_is64) {
        const longlong2* p = (const longlong2*)((const long long*)ei + EE + e0);
        longlong2 a = p[0], b = p[1];
        c0 = (int)a.x; c1 = (int)a.y; c2 = (int)b.x; c3 = (int)b.y;
    } else {
        int4 v = *(const int4*)((const int*)ei + EE + e0);
        c0 = v.x; c1 = v.y; c2 = v.z; c3 = v.w;
    }
    atomicAdd(&g_degi[c0], 1);
    atomicAdd(&g_degi[c1], 1);
    atomicAdd(&g_degi[c2], 1);
    atomicAdd(&g_degi[c3], 1);
}

// ---------------- scan stage 1 (block-local) + dinv fused ----------------------
__global__ void k_scan1() {
    __shared__ int s[256];
    int i = blockIdx.x * 256 + threadIdx.x;
    int v = (i < NN) ? g_degi[i] : 0;
    if (i < NN) g_dinv[i] = rsqrtf((float)(v + 1));   // +1 self loop
    s[threadIdx.x] = v;
    __syncthreads();
    for (int off = 1; off < 256; off <<= 1) {
        int add = (threadIdx.x >= off) ? s[threadIdx.x - off] : 0;
        __syncthreads();
        s[threadIdx.x] += add;
        __syncthreads();
    }
    if (i < NN) g_ptr[i] = s[threadIdx.x] - v;
    if (threadIdx.x == 255) g_bsum[blockIdx.x] = s[255];
}

// ---------------- scan stages 2+3 fused: each block reduces its own prefix ------
__global__ void k_scan23() {
    __shared__ int red[256];
    int bid = blockIdx.x;
    int sum = 0;
    for (int b = threadIdx.x; b < bid; b += 256) sum += g_bsum[b];
    red[threadIdx.x] = sum;
    __syncthreads();
    for (int st = 128; st > 0; st >>= 1) {
        if (threadIdx.x < st) red[threadIdx.x] += red[threadIdx.x + st];
        __syncthreads();
    }
    int pref = red[0];
    int i = bid * 256 + threadIdx.x;
    if (i < NN) {
        int p = g_ptr[i] + pref;
        g_ptr[i] = p;
        g_cursor[i] = p;
    }
    if (i == 0) g_ptr[NN] = EE;
}

// ---------------- CSR fill: bucket rows by col (4 edges/thread) -----------------
__global__ void k_fill(const void* __restrict__ ei) {
    long long e0 = 4LL * (blockIdx.x * blockDim.x + threadIdx.x);
    if (e0 >= EE) return;
    int r0, r1, r2, r3, c0, c1, c2, c3;
    if (g_is64) {
        const longlong2* pr = (const longlong2*)((const long long*)ei + e0);
        const longlong2* pc = (const longlong2*)((const long long*)ei + EE + e0);
        longlong2 ra = pr[0], rb = pr[1], ca = pc[0], cb = pc[1];
        r0 = (int)ra.x; r1 = (int)ra.y; r2 = (int)rb.x; r3 = (int)rb.y;
        c0 = (int)ca.x; c1 = (int)ca.y; c2 = (int)cb.x; c3 = (int)cb.y;
    } else {
        int4 rv = *(const int4*)((const int*)ei + e0);
        int4 cv = *(const int4*)((const int*)ei + EE + e0);
        r0 = rv.x; r1 = rv.y; r2 = rv.z; r3 = rv.w;
        c0 = cv.x; c1 = cv.y; c2 = cv.z; c3 = cv.w;
    }
    g_csr[atomicAdd(&g_cursor[c0], 1)] = r0;
    g_csr[atomicAdd(&g_cursor[c1], 1)] = r1;
    g_csr[atomicAdd(&g_cursor[c2], 1)] = r2;
    g_csr[atomicAdd(&g_cursor[c3], 1)] = r3;
}

// ---------------- tensor-core GEMM: bufA = fp16(dinv ⊙ (X(N,K) @ W(K,64))) -----
// 256 threads / 8 warps, block tile 128 rows x 64 cols, K chunked by 64.
template <int K, bool FIRST>
__global__ void k_gemm_tc(const float* __restrict__ W, const float* __restrict__ Xf) {
    constexpr int LDX = 72;   // 64 + 8 halfs pad
    __shared__ __half sX[128 * LDX];
    __shared__ __half sW[64 * LDX];

    const int tid  = threadIdx.x;
    const int wid  = tid >> 5;
    const int lane = tid & 31;
    const int row0 = blockIdx.x * 128;
    const int wr0  = wid * 16;          // warp row offset within tile

    float acc[8][4];
#pragma unroll
    for (int n = 0; n < 8; ++n)
#pragma unroll
        for (int i = 0; i < 4; ++i) acc[n][i] = 0.0f;

    const uint32_t sX_base = (uint32_t)__cvta_generic_to_shared(sX);
    const uint32_t sW_base = (uint32_t)__cvta_generic_to_shared(sW);

    for (int kt = 0; kt < K; kt += 64) {
        if (FIRST) {
            // fp32 global -> fp16 smem: 128 rows x 64 floats
#pragma unroll
            for (int it = 0; it < 8; ++it) {
                int idx = it * 256 + tid;        // 0..2047
                int r = idx >> 4, f4 = idx & 15;
                int grow = row0 + r;
                float4 v = make_float4(0.f, 0.f, 0.f, 0.f);
                if (grow < NN) v = *(const float4*)(Xf + (long long)grow * K + kt + f4 * 4);
                __half2 h0 = __floats2half2_rn(v.x, v.y);
                __half2 h1 = __floats2half2_rn(v.z, v.w);
                uint2 u;
                u.x = *(unsigned int*)&h0;
                u.y = *(unsigned int*)&h1;
                *(uint2*)(sX + r * LDX + f4 * 4) = u;
            }
        } else {
            // fp16 global -> smem: 128 rows x 64 halfs
#pragma unroll
            for (int it = 0; it < 4; ++it) {
                int idx = it * 256 + tid;        // 0..1023
                int r = idx >> 3, ch = idx & 7;
                int grow = row0 + r;
                uint4 u = make_uint4(0, 0, 0, 0);
                if (grow < NN) u = *(const uint4*)(g_bufBh + (long long)grow * K + kt + ch * 8);
                *(uint4*)(sX + r * LDX + ch * 8) = u;
            }
        }
        // load + convert W tile: 64 x 64
#pragma unroll
        for (int it = 0; it < 16; ++it) {
            int idx = it * 256 + tid;            // 0..4095
            int k = idx >> 6, n = idx & 63;
            sW[k * LDX + n] = __float2half(W[(kt + k) * HH + n]);
        }
        __syncthreads();

#pragma unroll
        for (int ks = 0; ks < 64; ks += 16) {
            uint32_t a[4];
            {
                int r = wr0 + (lane & 15);
                int kk = ks + ((lane >> 4) * 8);
                ldsm_x4(a, sX_base + (r * LDX + kk) * 2);
            }
#pragma unroll
            for (int np = 0; np < 4; ++np) {     // n-pairs: (np*16, np*16+8)
                uint32_t b[4];
                int krow = ks + (lane & 7) + (((lane >> 3) & 1) * 8);
                int ncol = np * 16 + ((lane >> 4) * 8);
                ldsm_x4_t(b, sW_base + (krow * LDX + ncol) * 2);
                mma_16816(acc[np * 2 + 0], a, b + 0);
                mma_16816(acc[np * 2 + 1], a, b + 2);
            }
        }
        __syncthreads();
    }

    // epilogue: scale by dinv, store fp16 to g_bufA
    const int rlo = row0 + wr0 + (lane >> 2);
    const int rhi = rlo + 8;
    const int cb  = (lane & 3) * 2;
    float dlo = (rlo < NN) ? g_dinv[rlo] : 0.0f;
    float dhi = (rhi < NN) ? g_dinv[rhi] : 0.0f;
#pragma unroll
    for (int nt = 0; nt < 8; ++nt) {
        int col = nt * 8 + cb;
        if (rlo < NN) {
            __half2 h = __floats2half2_rn(acc[nt][0] * dlo, acc[nt][1] * dlo);
            *(__half2*)(g_bufA + (long long)rlo * HH + col) = h;
        }
        if (rhi < NN) {
            __half2 h = __floats2half2_rn(acc[nt][2] * dhi, acc[nt][3] * dhi);
            *(__half2*)(g_bufA + (long long)rhi * HH + col) = h;
        }
    }
}

// ---------------- CSR gather: 8 lanes per node, one uint4 (8-half) chunk each ----
// !LAST: bufBh[i] = fp16(dinv[i]*(bufA[i] + Σ bufA[nbr]) + bias)
//  LAST: RED dinv[i]*(...) into g_pool[batch[i]] (+ cnt)
__device__ __forceinline__ void acc_half8(float4& a0, float4& a1, uint4 u) {
    float2 f0 = __half22float2(*(__half2*)&u.x);
    float2 f1 = __half22float2(*(__half2*)&u.y);
    float2 f2 = __half22float2(*(__half2*)&u.z);
    float2 f3 = __half22float2(*(__half2*)&u.w);
    a0.x += f0.x; a0.y += f0.y; a0.z += f1.x; a0.w += f1.y;
    a1.x += f2.x; a1.y += f2.y; a1.z += f3.x; a1.w += f3.y;
}

template <bool LAST>
__global__ void k_gather(const float* __restrict__ bias, const void* __restrict__ batch) {
    int t = blockIdx.x * blockDim.x + threadIdx.x;   // NN*8 exact
    int i = t >> 3;
    int c = t & 7;
    int lane = threadIdx.x & 31;
    int sub  = lane & 7;
    int base = lane & ~7;
    unsigned mask = 0xFFu << base;

    int start = g_ptr[i];
    int end   = g_ptr[i + 1];

    const uint4* __restrict__ A = (const uint4*)g_bufA;
    float4 a0 = make_float4(0.f, 0.f, 0.f, 0.f);
    float4 a1 = make_float4(0.f, 0.f, 0.f, 0.f);
    acc_half8(a0, a1, A[i * 8 + c]);   // self loop

    for (int p0 = start; p0 < end; p0 += 8) {
        int myj = 0;
        if (p0 + sub < end) myj = g_csr[p0 + sub];
        int cnt = min(8, end - p0);
        if (cnt == 8) {
#pragma unroll
            for (int k = 0; k < 8; ++k) {
                int j = __shfl_sync(mask, myj, k, 8);
                acc_half8(a0, a1, A[j * 8 + c]);
            }
        } else {
            for (int k = 0; k < cnt; ++k) {
                int j = __shfl_sync(mask, myj, k, 8);
                acc_half8(a0, a1, A[j * 8 + c]);
            }
        }
    }

    float d = g_dinv[i];
    if (LAST) {
        a0.x *= d; a0.y *= d; a0.z *= d; a0.w *= d;
        a1.x *= d; a1.y *= d; a1.z *= d; a1.w *= d;
        int b = 0;
        if (sub == 0) b = load_idx(batch, i);
        b = __shfl_sync(mask, b, 0, 8);
        float* dst = &g_pool[b * HH + c * 8];
        red_add_v4((float4*)dst, a0);
        red_add_v4((float4*)(dst + 4), a1);
        if (c == 0) atomicAdd(&g_cnt[b], 1.0f);
    } else {
        float4 b0 = ((const float4*)bias)[c * 2];
        float4 b1 = ((const float4*)bias)[c * 2 + 1];
        __half2 h0 = __floats2half2_rn(a0.x * d + b0.x, a0.y * d + b0.y);
        __half2 h1 = __floats2half2_rn(a0.z * d + b0.z, a0.w * d + b0.w);
        __half2 h2 = __floats2half2_rn(a1.x * d + b1.x, a1.y * d + b1.y);
        __half2 h3 = __floats2half2_rn(a1.z * d + b1.z, a1.w * d + b1.w);
        uint4 u;
        u.x = *(unsigned int*)&h0;
        u.y = *(unsigned int*)&h1;
        u.z = *(unsigned int*)&h2;
        u.w = *(unsigned int*)&h3;
        ((uint4*)g_bufBh)[i * 8 + c] = u;
    }
}

// ---------------- head: out(G,C) = (pool/cnt + b3) @ Wl + bl --------------------
__global__ void k_final(const float* __restrict__ Wl, const float* __restrict__ bl,
                        const float* __restrict__ b3, float* __restrict__ out) {
    int t = blockIdx.x * blockDim.x + threadIdx.x;
    if (t >= GG * CC) return;
    int g = t / CC, c = t % CC;
    float cnt = g_cnt[g];
    float inv = (cnt > 0.0f) ? (1.0f / cnt) : 0.0f;
    float sel = (cnt > 0.0f) ? 1.0f : 0.0f;
    float dot = 0.0f;
#pragma unroll
    for (int h = 0; h < HH; ++h)
        dot += (g_pool[g * HH + h] * inv + b3[h] * sel) * Wl[h * CC + c];
    out[t] = dot + bl[c];
}

// ---------------- launch ---------------------------------------------------------
extern "C" void kernel_launch(void* const* d_in, const int* in_sizes, int n_in,
                              void* d_out, int out_size) {
    const float* x  = (const float*)d_in[0];
    const void*  ei = d_in[1];
    const void*  bt = d_in[2];
    const float* W1 = (const float*)d_in[3];
    const float* b1 = (const float*)d_in[4];
    const float* W2 = (const float*)d_in[5];
    const float* b2 = (const float*)d_in[6];
    const float* W3 = (const float*)d_in[7];
    const float* b3 = (const float*)d_in[8];
    const float* Wl = (const float*)d_in[9];
    const float* bl = (const float*)d_in[10];
    float* out = (float*)d_out;

    const int TPB   = 256;
    const int gE4   = (EE / 4 + TPB - 1) / TPB;       // 1563
    const int gGth  = NN * 8 / TPB;                   // 3125 exact
    const int gGemm = (NN + 127) / 128;               // 782

    // 1) zero + detect, degrees, dinv, CSR build
    k_zero_all <<<SCAN_BLOCKS, TPB>>>((const unsigned int*)ei);
    k_deg_count<<<gE4, TPB>>>(ei);
    k_scan1    <<<SCAN_BLOCKS, 256>>>();
    k_scan23   <<<SCAN_BLOCKS, 256>>>();
    k_fill     <<<gE4, TPB>>>(ei);

    // 2) layer 1 (reads fp32 x directly)
    k_gemm_tc<DD, true><<<gGemm, TPB>>>(W1, x);
    k_gather<false><<<gGth, TPB>>>(b1, nullptr);

    // 3) layer 2
    k_gemm_tc<HH, false><<<gGemm, TPB>>>(W2, nullptr);
    k_gather<false><<<gGth, TPB>>>(b2, nullptr);

    // 4) layer 3 (gather fused with mean-pool accumulation)
    k_gemm_tc<HH, false><<<gGemm, TPB>>>(W3, nullptr);
    k_gather<true><<<gGth, TPB>>>(nullptr, bt);

    // 5) linear head (b3 folded in)
    k_final<<<(GG * CC + TPB - 1) / TPB, TPB>>>(Wl, bl, b3, out);
}